// round 3
// baseline (speedup 1.0000x reference)
#include <cuda_runtime.h>
#include <math.h>

#define Bn 512
#define Tn 128
#define En 128
#define Hn 256
#define G4 1024
#define KTAGS 10

typedef unsigned long long ull;

// ---------------- scratch (static device globals; no allocation) ----------------
__device__ float g_hall[(size_t)Bn * Tn * 2 * Hn];   // [b][t][512] concat(fwd,bwd)
__device__ float g_hstate[2][2][Bn][Hn];             // [ping][dir][b][h]
__device__ float g_c[2][Bn][Hn];                     // [dir][b][h]
__device__ int   g_len[Bn];
__device__ float g_WU[2][384][G4];                   // permuted [dir][k:(W rows 0-127, U rows 128-383)][n=cell*4+gate]
__device__ float g_bp[2][G4];                        // permuted bias

// ---------------- f32x2 packed helpers ----------------
__device__ __forceinline__ ull pk(float lo, float hi) {
    ull r; asm("mov.b64 %0, {%1, %2};" : "=l"(r) : "f"(lo), "f"(hi)); return r;
}
__device__ __forceinline__ void ffma2(ull& d, ull a, ull b) {
    asm("fma.rn.f32x2 %0, %1, %2, %0;" : "+l"(d) : "l"(a), "l"(b));
}
__device__ __forceinline__ float upk_lo(ull v) { return __uint_as_float((unsigned)(v & 0xffffffffULL)); }
__device__ __forceinline__ float upk_hi(ull v) { return __uint_as_float((unsigned)(v >> 32)); }
__device__ __forceinline__ float sigm(float x) { return 1.0f / (1.0f + expf(-x)); }

// ---------------- weight permutation + lengths (once per launch) ----------------
__global__ void __launch_bounds__(256)
prep_kernel(const int* __restrict__ word,
            const float* __restrict__ Wf, const float* __restrict__ Uf, const float* __restrict__ bf,
            const float* __restrict__ Wb, const float* __restrict__ Ub, const float* __restrict__ bb,
            float* __restrict__ out_len)
{
    int idx = blockIdx.x * 256 + threadIdx.x;
    int total = 2 * 384 * G4;
    if (idx < total) {
        int dir = idx / (384 * G4);
        int rem = idx % (384 * G4);
        int row = rem / G4;
        int n   = rem % G4;
        int col = (n & 3) * Hn + (n >> 2);
        float v;
        if (row < 128) v = (dir ? Wb : Wf)[row * G4 + col];
        else           v = (dir ? Ub : Uf)[(row - 128) * G4 + col];
        g_WU[dir][row][n] = v;
    }
    if (idx < 2 * G4) {
        int dir = idx >> 10, n = idx & 1023;
        int col = (n & 3) * Hn + (n >> 2);
        g_bp[dir][n] = (dir ? bb : bf)[col];
    }
    if (idx < Bn) {
        const int* w = word + (size_t)idx * Tn;
        int c = 0;
        #pragma unroll 8
        for (int t = 0; t < Tn; t++) c += (w[t] != 0);
        g_len[idx] = c;
        out_len[idx] = (float)c;
    }
}

// ---------------- fused LSTM step ----------------
// grid (8 batch tiles of 64, 16 cell chunks of 16, 2 dirs) = 512... -> (8,16,2)=256 CTAs, 256 thr.
// Tile 64 rows x 64 gate cols (16 cells). 2 CTAs/SM.
struct StepSmem {
    ull   A[2][32][64];     // [buf][k][m] duplicated (a,a)
    float B[2][32][64];     // [buf][k][n] permuted gate columns
};

__global__ void __launch_bounds__(256)
lstm_step(int s,
          const int* __restrict__ word,
          const float* __restrict__ emb)
{
    extern __shared__ char smem_raw[];
    StepSmem* S = (StepSmem*)smem_raw;

    const int dir = blockIdx.z;
    const int t   = dir ? (Tn - 1 - s) : s;
    const int b0  = blockIdx.x * 64;
    const int n_base = blockIdx.y * 64;     // gate-col base
    const int j0  = blockIdx.y * 16;        // cell base

    const int tid = threadIdx.x;
    const int tx = tid & 15;                // cell within chunk
    const int ty = tid >> 4;                // 0..15 -> rows ty*4..ty*4+3

    // loader roles
    const int am  = tid & 63;               // A row
    const int ak0 = (tid >> 6) * 8;         // A k offset
    const int bk  = tid >> 3;               // B k row (0..31)
    const int bn0 = (tid & 7) * 8;          // B n offset

    const int ping = s & 1;
    const float* hprev = &g_hstate[ping][dir][0][0];
    const int nch = (s == 0) ? 4 : 12;

    // acc init from permuted bias (bit-cast pairs, no movs)
    ull acc[4][2];
    {
        ulonglong2 bp = *(const ulonglong2*)&g_bp[dir][n_base + tx * 4];
        #pragma unroll
        for (int r = 0; r < 4; r++) { acc[r][0] = bp.x; acc[r][1] = bp.y; }
    }

    // A source base pointers
    const int wtok = __ldg(&word[(size_t)(b0 + am) * Tn + t]);
    const float* aph1 = emb + (size_t)wtok * En + ak0;                 // advance +32/chunk
    const float* aph2 = hprev + (size_t)(b0 + am) * Hn + ak0;          // advance +32/chunk from chunk 4
    const float* bsrc0 = &g_WU[dir][bk][n_base + bn0];                 // advance +32*G4/chunk

    float4 ra0, ra1, rb0, rb1;
    auto rload = [&](int kc) {
        const int kb = kc * 32;
        const float* ap = (kb < 128) ? (aph1 + kb) : (aph2 + (kb - 128));
        ra0 = *(const float4*)ap;
        ra1 = *(const float4*)(ap + 4);
        const float* bp = bsrc0 + (size_t)kb * G4;
        rb0 = *(const float4*)bp;
        rb1 = *(const float4*)(bp + 4);
    };
    auto rstore = [&](int buf) {
        S->A[buf][ak0 + 0][am] = pk(ra0.x, ra0.x);
        S->A[buf][ak0 + 1][am] = pk(ra0.y, ra0.y);
        S->A[buf][ak0 + 2][am] = pk(ra0.z, ra0.z);
        S->A[buf][ak0 + 3][am] = pk(ra0.w, ra0.w);
        S->A[buf][ak0 + 4][am] = pk(ra1.x, ra1.x);
        S->A[buf][ak0 + 5][am] = pk(ra1.y, ra1.y);
        S->A[buf][ak0 + 6][am] = pk(ra1.z, ra1.z);
        S->A[buf][ak0 + 7][am] = pk(ra1.w, ra1.w);
        *(float4*)&S->B[buf][bk][bn0]     = rb0;
        *(float4*)&S->B[buf][bk][bn0 + 4] = rb1;
    };

    rload(0); rstore(0);
    __syncthreads();

    for (int kc = 0; kc < nch; kc++) {
        const int buf = kc & 1;
        if (kc + 1 < nch) rload(kc + 1);

        #pragma unroll 8
        for (int kl = 0; kl < 32; kl++) {
            ulonglong2 a01 = *(const ulonglong2*)&S->A[buf][kl][ty * 4];
            ulonglong2 a23 = *(const ulonglong2*)&S->A[buf][kl][ty * 4 + 2];
            ulonglong2 bv  = *(const ulonglong2*)&S->B[buf][kl][tx * 4];
            ffma2(acc[0][0], a01.x, bv.x);
            ffma2(acc[0][1], a01.x, bv.y);
            ffma2(acc[1][0], a01.y, bv.x);
            ffma2(acc[1][1], a01.y, bv.y);
            ffma2(acc[2][0], a23.x, bv.x);
            ffma2(acc[2][1], a23.x, bv.y);
            ffma2(acc[3][0], a23.y, bv.x);
            ffma2(acc[3][1], a23.y, bv.y);
        }
        if (kc + 1 < nch) {
            rstore(buf ^ 1);
            __syncthreads();
        }
    }

    // ---- pointwise LSTM epilogue ----
    const int pingW = ping ^ 1;
    const int jj = j0 + tx;
    #pragma unroll
    for (int r = 0; r < 4; r++) {
        const int b = b0 + ty * 4 + r;
        float iv = upk_lo(acc[r][0]), fv = upk_hi(acc[r][0]);
        float gv = upk_lo(acc[r][1]), ov = upk_hi(acc[r][1]);
        float cp = (s == 0) ? 0.0f : g_c[dir][b][jj];
        float ii = sigm(iv);
        float ff = sigm(fv);
        float gg = tanhf(gv);
        float oo = sigm(ov);
        float cn = ff * cp + ii * gg;
        float hn = oo * tanhf(cn);
        g_c[dir][b][jj] = cn;
        g_hstate[pingW][dir][b][jj] = hn;
        g_hall[((size_t)b * Tn + t) * (2 * Hn) + dir * Hn + jj] = hn;
    }
}

// ---------------- dense + softmax ----------------
__global__ void __launch_bounds__(256)
dense_softmax(const float* __restrict__ Wd, const float* __restrict__ bd, float* __restrict__ probs)
{
    __shared__ float wd_s[KTAGS][2 * Hn];
    __shared__ float bd_s[KTAGS];
    const int tid = threadIdx.x;
    for (int i = tid; i < 2 * Hn * KTAGS; i += 256) {
        int e = i / KTAGS, k = i % KTAGS;
        wd_s[k][e] = Wd[i];
    }
    if (tid < KTAGS) bd_s[tid] = bd[tid];
    __syncthreads();

    const int warp = tid >> 5, lane = tid & 31;
    const size_t row = (size_t)blockIdx.x * 8 + warp;
    const float* h = &g_hall[row * (2 * Hn)];

    float acc[KTAGS];
    #pragma unroll
    for (int k = 0; k < KTAGS; k++) acc[k] = 0.0f;

    #pragma unroll
    for (int q = 0; q < 16; q++) {
        int e = lane + 32 * q;
        float hv = h[e];
        #pragma unroll
        for (int k = 0; k < KTAGS; k++) acc[k] += hv * wd_s[k][e];
    }
    #pragma unroll
    for (int k = 0; k < KTAGS; k++) {
        #pragma unroll
        for (int off = 16; off > 0; off >>= 1)
            acc[k] += __shfl_xor_sync(0xffffffffu, acc[k], off);
        acc[k] += bd_s[k];
    }
    float mx = acc[0];
    #pragma unroll
    for (int k = 1; k < KTAGS; k++) mx = fmaxf(mx, acc[k]);
    float den = 0.0f;
    #pragma unroll
    for (int k = 0; k < KTAGS; k++) den += expf(acc[k] - mx);
    float inv = 1.0f / den;
    #pragma unroll
    for (int k = 0; k < KTAGS; k++) {
        float pv = expf(acc[k] - mx) * inv;
        if (lane == k) probs[row * KTAGS + k] = pv;
    }
}

// ---------------- CRF log-likelihood ----------------
__global__ void crf_kernel(const int* __restrict__ label,
                           const float* __restrict__ trans,
                           const float* __restrict__ probs,
                           float* __restrict__ out_ll)
{
    const int b = blockIdx.x;
    const int lane = threadIdx.x;
    const int len = g_len[b];
    const float* P = probs + (size_t)b * Tn * KTAGS;
    const int* tg = label + (size_t)b * Tn;

    float u = 0.0f;
    for (int t = lane; t < Tn; t += 32)
        if (t < len) u += P[t * KTAGS + tg[t]];
    float bi = 0.0f;
    for (int t = lane; t < Tn - 1; t += 32)
        if (t < len - 1) bi += trans[tg[t] * KTAGS + tg[t + 1]];
    #pragma unroll
    for (int off = 16; off > 0; off >>= 1) {
        u  += __shfl_xor_sync(0xffffffffu, u, off);
        bi += __shfl_xor_sync(0xffffffffu, bi, off);
    }

    const int kk = (lane < KTAGS) ? lane : 0;
    float tr[KTAGS];
    #pragma unroll
    for (int j = 0; j < KTAGS; j++) tr[j] = trans[j * KTAGS + kk];

    float alpha = (lane < KTAGS) ? P[kk] : -1e30f;
    for (int t = 1; t < Tn; t++) {
        float aj[KTAGS];
        #pragma unroll
        for (int j = 0; j < KTAGS; j++) aj[j] = __shfl_sync(0xffffffffu, alpha, j);
        float m = -1e30f;
        #pragma unroll
        for (int j = 0; j < KTAGS; j++) m = fmaxf(m, aj[j] + tr[j]);
        float sum = 0.0f;
        #pragma unroll
        for (int j = 0; j < KTAGS; j++) sum += expf(aj[j] + tr[j] - m);
        float nv = m + logf(sum) + P[t * KTAGS + kk];
        if (t < len && lane < KTAGS) alpha = nv;
    }
    float aj[KTAGS];
    #pragma unroll
    for (int j = 0; j < KTAGS; j++) aj[j] = __shfl_sync(0xffffffffu, alpha, j);
    float m = -1e30f;
    #pragma unroll
    for (int j = 0; j < KTAGS; j++) m = fmaxf(m, aj[j]);
    float sum = 0.0f;
    #pragma unroll
    for (int j = 0; j < KTAGS; j++) sum += expf(aj[j] - m);
    float ln = (len == 0) ? 0.0f : (m + logf(sum));

    if (lane == 0) out_ll[b] = u + bi - ln;
}

// ---------------- launch ----------------
extern "C" void kernel_launch(void* const* d_in, const int* in_sizes, int n_in,
                              void* d_out, int out_size)
{
    const int*   word  = (const int*)d_in[0];
    const int*   label = (const int*)d_in[1];
    const float* emb   = (const float*)d_in[2];
    const float* Wf    = (const float*)d_in[3];
    const float* Uf    = (const float*)d_in[4];
    const float* bf    = (const float*)d_in[5];
    const float* Wb    = (const float*)d_in[6];
    const float* Ub    = (const float*)d_in[7];
    const float* bb    = (const float*)d_in[8];
    const float* Wd    = (const float*)d_in[9];
    const float* bd    = (const float*)d_in[10];
    const float* trans = (const float*)d_in[11];

    float* out      = (float*)d_out;
    float* probs    = out;                                 // 512*128*10
    float* out_len  = out + (size_t)Bn * Tn * KTAGS;       // 512
    float* out_ll   = out_len + Bn;                        // 512

    const int smem_bytes = (int)sizeof(StepSmem);
    cudaFuncSetAttribute(lstm_step, cudaFuncAttributeMaxDynamicSharedMemorySize, smem_bytes);

    // prep: permute weights/bias + lengths
    prep_kernel<<<(2 * 384 * G4 + 255) / 256, 256>>>(word, Wf, Uf, bf, Wb, Ub, bb, out_len);

    dim3 grid(8, 16, 2);
    for (int s = 0; s < Tn; s++)
        lstm_step<<<grid, 256, smem_bytes>>>(s, word, emb);

    dense_softmax<<<8192, 256>>>(Wd, bd, probs);
    crf_kernel<<<Bn, 32>>>(label, trans, probs, out_ll);
}

// round 4
// speedup vs baseline: 1.1002x; 1.1002x over previous
#include <cuda_runtime.h>
#include <math.h>

#define Bn 512
#define Tn 128
#define En 128
#define Hn 256
#define G4 1024
#define KTAGS 10

typedef unsigned long long ull;

// ---------------- scratch (static device globals; no allocation) ----------------
__device__ float g_hall[(size_t)Bn * Tn * 2 * Hn];   // [b][t][512] concat(fwd,bwd)
__device__ float g_hstate[2][2][Bn][Hn];             // [ping][dir][b][h]
__device__ float g_c[2][Bn][Hn];                     // [dir][b][h]
__device__ int   g_len[Bn];
__device__ float g_WU[2][384][G4];                   // permuted [dir][k (W:0-127, U:128-383)][n=cell*4+gate]
__device__ float g_bp[2][G4];                        // permuted bias

// ---------------- f32x2 packed helpers ----------------
__device__ __forceinline__ ull pk(float lo, float hi) {
    ull r; asm("mov.b64 %0, {%1, %2};" : "=l"(r) : "f"(lo), "f"(hi)); return r;
}
__device__ __forceinline__ void ffma2(ull& d, ull a, ull b) {
    asm("fma.rn.f32x2 %0, %1, %2, %0;" : "+l"(d) : "l"(a), "l"(b));
}
__device__ __forceinline__ ull add2(ull a, ull b) {
    ull r; asm("add.rn.f32x2 %0, %1, %2;" : "=l"(r) : "l"(a), "l"(b)); return r;
}
__device__ __forceinline__ float upk_lo(ull v) { return __uint_as_float((unsigned)(v & 0xffffffffULL)); }
__device__ __forceinline__ float upk_hi(ull v) { return __uint_as_float((unsigned)(v >> 32)); }
__device__ __forceinline__ float sigm(float x) { return 1.0f / (1.0f + expf(-x)); }

// ---------------- weight permutation + lengths (once per launch) ----------------
__global__ void __launch_bounds__(256)
prep_kernel(const int* __restrict__ word,
            const float* __restrict__ Wf, const float* __restrict__ Uf, const float* __restrict__ bf,
            const float* __restrict__ Wb, const float* __restrict__ Ub, const float* __restrict__ bb,
            float* __restrict__ out_len)
{
    int idx = blockIdx.x * 256 + threadIdx.x;
    int total = 2 * 384 * G4;
    if (idx < total) {
        int dir = idx / (384 * G4);
        int rem = idx % (384 * G4);
        int row = rem / G4;
        int n   = rem % G4;
        int col = (n & 3) * Hn + (n >> 2);
        float v;
        if (row < 128) v = (dir ? Wb : Wf)[row * G4 + col];
        else           v = (dir ? Ub : Uf)[(row - 128) * G4 + col];
        g_WU[dir][row][n] = v;
    }
    if (idx < 2 * G4) {
        int dir = idx >> 10, n = idx & 1023;
        int col = (n & 3) * Hn + (n >> 2);
        g_bp[dir][n] = (dir ? bb : bf)[col];
    }
    if (idx < Bn) {
        const int* w = word + (size_t)idx * Tn;
        int c = 0;
        #pragma unroll 8
        for (int t = 0; t < Tn; t++) c += (w[t] != 0);
        g_len[idx] = c;
        out_len[idx] = (float)c;
    }
}

// ---------------- fused LSTM step, K-split across 2 warp-groups ----------------
// grid (8 batch tiles, 8 cell chunks of 32, 2 dirs) = 128 CTAs, 512 threads.
// Tile 64 rows x 128 gate cols. Group g accumulates k in [g*192,(g+1)*192).
// SMEM layout (manual offsets, 128KB):
//   A(g,buf): ull[32][64]  at (g*2+buf)*16384           (dup'd (a,a) pairs)
//   B(g,buf): float[32][128] at 65536+(g*2+buf)*16384
//   reduce:   R1 (grp1 acc, 32KB) at 0 ; R0 (grp0 rows2-3, 16KB) at 32768  [reuses A]
#define SM_TOTAL 131072

__global__ void __launch_bounds__(512)
lstm_step(int s,
          const int* __restrict__ word,
          const float* __restrict__ emb)
{
    extern __shared__ char sm[];

    const int dir = blockIdx.z;
    const int t   = dir ? (Tn - 1 - s) : s;
    const int b0  = blockIdx.x * 64;
    const int n_base = blockIdx.y * 128;    // gate-col base
    const int j0  = blockIdx.y * 32;        // cell base

    const int tid  = threadIdx.x;
    const int g    = tid >> 8;              // warp-group 0/1
    const int wtid = tid & 255;
    const int tx = wtid & 15;               // cells j0+tx, j0+16+tx
    const int ty = wtid >> 4;               // rows ty*4 .. ty*4+3

    // loader roles (within group)
    const int am  = wtid & 63;              // A row
    const int ak0 = (wtid >> 6) * 8;        // A k offset (0,8,16,24)
    const int bk  = wtid >> 3;              // B k row (0..31)
    const int bn0 = (wtid & 7) * 16;        // B n offset

    auto A_at = [&](int buf) -> ull*   { return (ull*)  (sm + (size_t)(g * 2 + buf) * 16384); };
    auto B_at = [&](int buf) -> float* { return (float*)(sm + 65536 + (size_t)(g * 2 + buf) * 16384); };

    const int ping = s & 1;
    const float* hprev = &g_hstate[ping][dir][0][0];
    const int nch = (s == 0) ? 2 : 6;             // chunks per group
    const int gk0 = g * ((s == 0) ? 64 : 192);    // group k base

    // acc[r][c][p]: r row 0..3, c cell half, p gate pair ((i,f),(g,o)).
    // Only group 0 seeds with bias (avoid double count after reduce).
    ull acc[4][2][2];
    if (g == 0) {
        #pragma unroll
        for (int c = 0; c < 2; c++) {
            ulonglong2 bp = *(const ulonglong2*)&g_bp[dir][n_base + (tx + 16 * c) * 4];
            #pragma unroll
            for (int r = 0; r < 4; r++) { acc[r][c][0] = bp.x; acc[r][c][1] = bp.y; }
        }
    } else {
        #pragma unroll
        for (int r = 0; r < 4; r++)
            #pragma unroll
            for (int c = 0; c < 2; c++) { acc[r][c][0] = 0; acc[r][c][1] = 0; }
    }

    // A global sources (contiguous k)
    const int wtok = __ldg(&word[(size_t)(b0 + am) * Tn + t]);
    const float* aph1 = emb + (size_t)wtok * En + ak0;
    const float* aph2 = hprev + (size_t)(b0 + am) * Hn + ak0;
    const float* bsrc0 = &g_WU[dir][0][n_base + bn0];

    float4 ra0, ra1, rb0, rb1, rb2, rb3;
    auto rload = [&](int kc) {
        const int kb = gk0 + kc * 32;
        const float* ap = (kb < 128) ? (aph1 + kb) : (aph2 + (kb - 128));
        ra0 = *(const float4*)ap;
        ra1 = *(const float4*)(ap + 4);
        const float* bp = bsrc0 + (size_t)(kb + bk) * G4;
        rb0 = *(const float4*)bp;
        rb1 = *(const float4*)(bp + 4);
        rb2 = *(const float4*)(bp + 8);
        rb3 = *(const float4*)(bp + 12);
    };
    auto rstore = [&](int buf) {
        ull* A = A_at(buf);
        A[(ak0 + 0) * 64 + am] = pk(ra0.x, ra0.x);
        A[(ak0 + 1) * 64 + am] = pk(ra0.y, ra0.y);
        A[(ak0 + 2) * 64 + am] = pk(ra0.z, ra0.z);
        A[(ak0 + 3) * 64 + am] = pk(ra0.w, ra0.w);
        A[(ak0 + 4) * 64 + am] = pk(ra1.x, ra1.x);
        A[(ak0 + 5) * 64 + am] = pk(ra1.y, ra1.y);
        A[(ak0 + 6) * 64 + am] = pk(ra1.z, ra1.z);
        A[(ak0 + 7) * 64 + am] = pk(ra1.w, ra1.w);
        float* B = B_at(buf);
        *(float4*)&B[bk * 128 + bn0]      = rb0;
        *(float4*)&B[bk * 128 + bn0 + 4]  = rb1;
        *(float4*)&B[bk * 128 + bn0 + 8]  = rb2;
        *(float4*)&B[bk * 128 + bn0 + 12] = rb3;
    };

    rload(0); rstore(0);
    __syncthreads();

    for (int kc = 0; kc < nch; kc++) {
        const int buf = kc & 1;
        if (kc + 1 < nch) rload(kc + 1);

        const ull* A = A_at(buf);
        const float* B = B_at(buf);
        #pragma unroll 8
        for (int kl = 0; kl < 32; kl++) {
            ulonglong2 a01 = *(const ulonglong2*)&A[kl * 64 + ty * 4];
            ulonglong2 a23 = *(const ulonglong2*)&A[kl * 64 + ty * 4 + 2];
            ulonglong2 b0v = *(const ulonglong2*)&B[kl * 128 + tx * 4];
            ulonglong2 b1v = *(const ulonglong2*)&B[kl * 128 + 64 + tx * 4];
            ffma2(acc[0][0][0], a01.x, b0v.x);
            ffma2(acc[0][0][1], a01.x, b0v.y);
            ffma2(acc[0][1][0], a01.x, b1v.x);
            ffma2(acc[0][1][1], a01.x, b1v.y);
            ffma2(acc[1][0][0], a01.y, b0v.x);
            ffma2(acc[1][0][1], a01.y, b0v.y);
            ffma2(acc[1][1][0], a01.y, b1v.x);
            ffma2(acc[1][1][1], a01.y, b1v.y);
            ffma2(acc[2][0][0], a23.x, b0v.x);
            ffma2(acc[2][0][1], a23.x, b0v.y);
            ffma2(acc[2][1][0], a23.x, b1v.x);
            ffma2(acc[2][1][1], a23.x, b1v.y);
            ffma2(acc[3][0][0], a23.y, b0v.x);
            ffma2(acc[3][0][1], a23.y, b0v.y);
            ffma2(acc[3][1][0], a23.y, b1v.x);
            ffma2(acc[3][1][1], a23.y, b1v.y);
        }
        if (kc + 1 < nch) rstore(buf ^ 1);
        __syncthreads();
    }

    // ---- cross-group reduce (reuses A SMEM region; all inner-loop reads done) ----
    ull* R1 = (ull*)sm;              // [256][16]
    ull* R0 = (ull*)(sm + 32768);    // [256][8]
    if (g == 1) {
        ull* dst = &R1[wtid * 16];
        #pragma unroll
        for (int r = 0; r < 4; r++)
            #pragma unroll
            for (int c = 0; c < 2; c++) {
                dst[r * 4 + c * 2 + 0] = acc[r][c][0];
                dst[r * 4 + c * 2 + 1] = acc[r][c][1];
            }
    } else {
        ull* dst = &R0[wtid * 8];
        #pragma unroll
        for (int r = 0; r < 2; r++)
            #pragma unroll
            for (int c = 0; c < 2; c++) {
                dst[r * 4 + c * 2 + 0] = acc[2 + r][c][0];
                dst[r * 4 + c * 2 + 1] = acc[2 + r][c][1];
            }
    }
    __syncthreads();

    // group 0 finalizes rows 0-1; group 1 rows 2-3
    ull tot[2][2][2];
    if (g == 0) {
        const ull* src = &R1[wtid * 16];
        #pragma unroll
        for (int r = 0; r < 2; r++)
            #pragma unroll
            for (int c = 0; c < 2; c++) {
                tot[r][c][0] = add2(acc[r][c][0], src[r * 4 + c * 2 + 0]);
                tot[r][c][1] = add2(acc[r][c][1], src[r * 4 + c * 2 + 1]);
            }
    } else {
        const ull* src = &R0[wtid * 8];
        #pragma unroll
        for (int r = 0; r < 2; r++)
            #pragma unroll
            for (int c = 0; c < 2; c++) {
                tot[r][c][0] = add2(acc[2 + r][c][0], src[r * 4 + c * 2 + 0]);
                tot[r][c][1] = add2(acc[2 + r][c][1], src[r * 4 + c * 2 + 1]);
            }
    }

    // ---- pointwise LSTM epilogue (2 rows x 2 cells per thread) ----
    const int pingW = ping ^ 1;
    #pragma unroll
    for (int r = 0; r < 2; r++) {
        const int b = b0 + ty * 4 + g * 2 + r;
        #pragma unroll
        for (int c = 0; c < 2; c++) {
            const int jj = j0 + tx + 16 * c;
            float iv = upk_lo(tot[r][c][0]), fv = upk_hi(tot[r][c][0]);
            float gv = upk_lo(tot[r][c][1]), ov = upk_hi(tot[r][c][1]);
            float cp = (s == 0) ? 0.0f : g_c[dir][b][jj];
            float ii = sigm(iv);
            float ff = sigm(fv);
            float gg = tanhf(gv);
            float oo = sigm(ov);
            float cn = ff * cp + ii * gg;
            float hn = oo * tanhf(cn);
            g_c[dir][b][jj] = cn;
            g_hstate[pingW][dir][b][jj] = hn;
            g_hall[((size_t)b * Tn + t) * (2 * Hn) + dir * Hn + jj] = hn;
        }
    }
}

// ---------------- dense + softmax ----------------
__global__ void __launch_bounds__(256)
dense_softmax(const float* __restrict__ Wd, const float* __restrict__ bd, float* __restrict__ probs)
{
    __shared__ float wd_s[KTAGS][2 * Hn];
    __shared__ float bd_s[KTAGS];
    const int tid = threadIdx.x;
    for (int i = tid; i < 2 * Hn * KTAGS; i += 256) {
        int e = i / KTAGS, k = i % KTAGS;
        wd_s[k][e] = Wd[i];
    }
    if (tid < KTAGS) bd_s[tid] = bd[tid];
    __syncthreads();

    const int warp = tid >> 5, lane = tid & 31;
    const size_t row = (size_t)blockIdx.x * 8 + warp;
    const float* h = &g_hall[row * (2 * Hn)];

    float acc[KTAGS];
    #pragma unroll
    for (int k = 0; k < KTAGS; k++) acc[k] = 0.0f;

    #pragma unroll
    for (int q = 0; q < 16; q++) {
        int e = lane + 32 * q;
        float hv = h[e];
        #pragma unroll
        for (int k = 0; k < KTAGS; k++) acc[k] += hv * wd_s[k][e];
    }
    #pragma unroll
    for (int k = 0; k < KTAGS; k++) {
        #pragma unroll
        for (int off = 16; off > 0; off >>= 1)
            acc[k] += __shfl_xor_sync(0xffffffffu, acc[k], off);
        acc[k] += bd_s[k];
    }
    float mx = acc[0];
    #pragma unroll
    for (int k = 1; k < KTAGS; k++) mx = fmaxf(mx, acc[k]);
    float den = 0.0f;
    #pragma unroll
    for (int k = 0; k < KTAGS; k++) den += expf(acc[k] - mx);
    float inv = 1.0f / den;
    #pragma unroll
    for (int k = 0; k < KTAGS; k++) {
        float pv = expf(acc[k] - mx) * inv;
        if (lane == k) probs[row * KTAGS + k] = pv;
    }
}

// ---------------- CRF log-likelihood ----------------
__global__ void crf_kernel(const int* __restrict__ label,
                           const float* __restrict__ trans,
                           const float* __restrict__ probs,
                           float* __restrict__ out_ll)
{
    const int b = blockIdx.x;
    const int lane = threadIdx.x;
    const int len = g_len[b];
    const float* P = probs + (size_t)b * Tn * KTAGS;
    const int* tg = label + (size_t)b * Tn;

    float u = 0.0f;
    for (int t = lane; t < Tn; t += 32)
        if (t < len) u += P[t * KTAGS + tg[t]];
    float bi = 0.0f;
    for (int t = lane; t < Tn - 1; t += 32)
        if (t < len - 1) bi += trans[tg[t] * KTAGS + tg[t + 1]];
    #pragma unroll
    for (int off = 16; off > 0; off >>= 1) {
        u  += __shfl_xor_sync(0xffffffffu, u, off);
        bi += __shfl_xor_sync(0xffffffffu, bi, off);
    }

    const int kk = (lane < KTAGS) ? lane : 0;
    float tr[KTAGS];
    #pragma unroll
    for (int j = 0; j < KTAGS; j++) tr[j] = trans[j * KTAGS + kk];

    float alpha = (lane < KTAGS) ? P[kk] : -1e30f;
    for (int t = 1; t < Tn; t++) {
        float aj[KTAGS];
        #pragma unroll
        for (int j = 0; j < KTAGS; j++) aj[j] = __shfl_sync(0xffffffffu, alpha, j);
        float m = -1e30f;
        #pragma unroll
        for (int j = 0; j < KTAGS; j++) m = fmaxf(m, aj[j] + tr[j]);
        float sum = 0.0f;
        #pragma unroll
        for (int j = 0; j < KTAGS; j++) sum += expf(aj[j] + tr[j] - m);
        float nv = m + logf(sum) + P[t * KTAGS + kk];
        if (t < len && lane < KTAGS) alpha = nv;
    }
    float aj[KTAGS];
    #pragma unroll
    for (int j = 0; j < KTAGS; j++) aj[j] = __shfl_sync(0xffffffffu, alpha, j);
    float m = -1e30f;
    #pragma unroll
    for (int j = 0; j < KTAGS; j++) m = fmaxf(m, aj[j]);
    float sum = 0.0f;
    #pragma unroll
    for (int j = 0; j < KTAGS; j++) sum += expf(aj[j] - m);
    float ln = (len == 0) ? 0.0f : (m + logf(sum));

    if (lane == 0) out_ll[b] = u + bi - ln;
}

// ---------------- launch ----------------
extern "C" void kernel_launch(void* const* d_in, const int* in_sizes, int n_in,
                              void* d_out, int out_size)
{
    const int*   word  = (const int*)d_in[0];
    const int*   label = (const int*)d_in[1];
    const float* emb   = (const float*)d_in[2];
    const float* Wf    = (const float*)d_in[3];
    const float* Uf    = (const float*)d_in[4];
    const float* bf    = (const float*)d_in[5];
    const float* Wb    = (const float*)d_in[6];
    const float* Ub    = (const float*)d_in[7];
    const float* bb    = (const float*)d_in[8];
    const float* Wd    = (const float*)d_in[9];
    const float* bd    = (const float*)d_in[10];
    const float* trans = (const float*)d_in[11];

    float* out      = (float*)d_out;
    float* probs    = out;                                 // 512*128*10
    float* out_len  = out + (size_t)Bn * Tn * KTAGS;       // 512
    float* out_ll   = out_len + Bn;                        // 512

    cudaFuncSetAttribute(lstm_step, cudaFuncAttributeMaxDynamicSharedMemorySize, SM_TOTAL);

    prep_kernel<<<(2 * 384 * G4 + 255) / 256, 256>>>(word, Wf, Uf, bf, Wb, Ub, bb, out_len);

    dim3 grid(8, 8, 2);
    for (int s = 0; s < Tn; s++)
        lstm_step<<<grid, 512, SM_TOTAL>>>(s, word, emb);

    dense_softmax<<<8192, 256>>>(Wd, bd, probs);
    crf_kernel<<<Bn, 32>>>(label, trans, probs, out_ll);
}